// round 2
// baseline (speedup 1.0000x reference)
#include <cuda_runtime.h>
#include <cuda_bf16.h>
#include <cstdint>

#define NUM_CLASSES 1000
#define D 512
#define N_MAX 131072

// ---------------- scratch (no allocations allowed) ----------------
__device__ int   g_counts[NUM_CLASSES];
__device__ int   g_offsets[NUM_CLASSES + 1];
__device__ int   g_cursor[NUM_CLASSES];
__device__ int   g_sorted[N_MAX];
__device__ float g_centers[NUM_CLASSES * D];
__device__ float g_sq[NUM_CLASSES];
__device__ int   g_minbits;   // float bits of min positive distance
__device__ int   g_lab64;     // 1 if labels are int64, 0 if int32
__device__ int   g_done;      // pairwise completion counter

__device__ __forceinline__ int load_label(const void* labels, int i, int is64) {
    if (is64) return (int)((const long long*)labels)[i];
    return ((const int*)labels)[i];
}

// K0: reset per-call state + label dtype sniff (single block)
__global__ void k_init(const void* labels) {
    int t = threadIdx.x;
    if (t < NUM_CLASSES) g_counts[t] = 0;
    if (t == 0) {
        g_minbits = 0x7F800000;  // +inf
        g_done = 0;
        g_lab64 = 1;
    }
    __syncthreads();
    if (t < 512) {
        long long v = ((const long long*)labels)[t];
        if (v < 0 || v >= NUM_CLASSES) g_lab64 = 0;
    }
}

// K1: histogram
__global__ void k_hist(const void* labels, int n) {
    int i = blockIdx.x * blockDim.x + threadIdx.x;
    int is64 = g_lab64;
    if (i < n) {
        int lab = load_label(labels, i, is64);
        atomicAdd(&g_counts[lab], 1);
    }
}

// K2: exclusive scan over 1000 counts (shfl warp-scan, 2 barriers)
__global__ void k_scan(int n) {
    __shared__ int wsum[32];
    int t = threadIdx.x;             // 0..1023
    int lane = t & 31, warp = t >> 5;
    int v = (t < NUM_CLASSES) ? g_counts[t] : 0;
    int x = v;
#pragma unroll
    for (int off = 1; off < 32; off <<= 1) {
        int y = __shfl_up_sync(0xFFFFFFFF, x, off);
        if (lane >= off) x += y;
    }
    if (lane == 31) wsum[warp] = x;
    __syncthreads();
    if (t < 32) {
        int w = wsum[t];
#pragma unroll
        for (int off = 1; off < 32; off <<= 1) {
            int y = __shfl_up_sync(0xFFFFFFFF, w, off);
            if (lane >= off) w += y;
        }
        wsum[t] = w;
    }
    __syncthreads();
    int base = (warp > 0) ? wsum[warp - 1] : 0;
    int excl = base + x - v;
    if (t < NUM_CLASSES) {
        g_offsets[t] = excl;
        g_cursor[t]  = excl;
    }
    if (t == 0) g_offsets[NUM_CLASSES] = n;
}

// K3: scatter row indices into class-sorted order
__global__ void k_scatter(const void* labels, int n) {
    int i = blockIdx.x * blockDim.x + threadIdx.x;
    int is64 = g_lab64;
    if (i < n) {
        int lab = load_label(labels, i, is64);
        int pos = atomicAdd(&g_cursor[lab], 1);
        g_sorted[pos] = i;
    }
}

// K4: per-class mean in registers (no atomics). Also reduces sq = sum(center^2).
__global__ void __launch_bounds__(D) k_classsum(const float* __restrict__ f) {
    int c = blockIdx.x;
    int t = threadIdx.x;  // column, 0..511
    int s = g_offsets[c], e = g_offsets[c + 1];
    int cnt = e - s;

    __shared__ int sidx[512];
    float a0 = 0.f, a1 = 0.f, a2 = 0.f, a3 = 0.f;
    float a4 = 0.f, a5 = 0.f, a6 = 0.f, a7 = 0.f;

    for (int base = s; base < e; base += 512) {
        int m = e - base; if (m > 512) m = 512;
        __syncthreads();
        if (t < m) sidx[t] = g_sorted[base + t];
        __syncthreads();
        int r = 0;
        for (; r + 8 <= m; r += 8) {
            long i0 = sidx[r],     i1 = sidx[r + 1], i2 = sidx[r + 2], i3 = sidx[r + 3];
            long i4 = sidx[r + 4], i5 = sidx[r + 5], i6 = sidx[r + 6], i7 = sidx[r + 7];
            a0 += __ldcs(&f[i0 * D + t]);
            a1 += __ldcs(&f[i1 * D + t]);
            a2 += __ldcs(&f[i2 * D + t]);
            a3 += __ldcs(&f[i3 * D + t]);
            a4 += __ldcs(&f[i4 * D + t]);
            a5 += __ldcs(&f[i5 * D + t]);
            a6 += __ldcs(&f[i6 * D + t]);
            a7 += __ldcs(&f[i7 * D + t]);
        }
        for (; r < m; r++) a0 += __ldcs(&f[(long)sidx[r] * D + t]);
    }
    float acc = ((a0 + a1) + (a2 + a3)) + ((a4 + a5) + (a6 + a7));
    float denom = fmaxf((float)cnt, 1.0f);
    float cen = acc / denom;
    g_centers[c * D + t] = cen;

    // tree-reduce cen^2 across 512 threads (order intentionally differs from
    // the pairwise sequential dot, mirroring the reference's sq vs matmul)
    float v = cen * cen;
#pragma unroll
    for (int off = 16; off > 0; off >>= 1)
        v += __shfl_down_sync(0xFFFFFFFF, v, off);
    __shared__ float ws[16];
    int warp = t >> 5, lane = t & 31;
    if (lane == 0) ws[warp] = v;
    __syncthreads();
    if (t < 16) {
        float w = ws[t];
#pragma unroll
        for (int off = 8; off > 0; off >>= 1)
            w += __shfl_down_sync(0xFFFF, w, off);
        if (t == 0) g_sq[c] = w;
    }
}

// K5: pairwise min over upper-triangle tiles + last-block finalize.
// dis = sq[i]+sq[j]-2*dot (incl. diagonal, filtered by >0, same as reference).
// Transposed smem tiles -> two 128-bit LDS per k-step per thread (A-side
// broadcasts within the warp), making the inner loop FMA-bound.
#define PT 64
#define KC 64
#define GRID_PW 16
__global__ void __launch_bounds__(256) k_pairwise(float* __restrict__ out) {
    int bi = blockIdx.x, bj = blockIdx.y;
    int tid = threadIdx.x;

    if (bj >= bi) {
        __shared__ float As[KC][PT + 4];
        __shared__ float Bs[KC][PT + 4];

        int tx = tid & 15;   // j micro index
        int ty = tid >> 4;   // i micro index

        float acc[4][4];
#pragma unroll
        for (int r = 0; r < 4; r++)
#pragma unroll
            for (int s2 = 0; s2 < 4; s2++) acc[r][s2] = 0.f;

        int rowb = tid >> 4;        // 0..15
        int kk   = (tid & 15) * 4;  // 0..60

        for (int k0 = 0; k0 < D; k0 += KC) {
            __syncthreads();
#pragma unroll
            for (int rr = 0; rr < 4; rr++) {
                int row = rowb + rr * 16;
                int gi = bi * PT + row;
                int gj = bj * PT + row;
                float4 av = (gi < NUM_CLASSES)
                    ? *(const float4*)&g_centers[gi * D + k0 + kk]
                    : make_float4(0.f, 0.f, 0.f, 0.f);
                float4 bv = (gj < NUM_CLASSES)
                    ? *(const float4*)&g_centers[gj * D + k0 + kk]
                    : make_float4(0.f, 0.f, 0.f, 0.f);
                As[kk + 0][row] = av.x; As[kk + 1][row] = av.y;
                As[kk + 2][row] = av.z; As[kk + 3][row] = av.w;
                Bs[kk + 0][row] = bv.x; Bs[kk + 1][row] = bv.y;
                Bs[kk + 2][row] = bv.z; Bs[kk + 3][row] = bv.w;
            }
            __syncthreads();
#pragma unroll 4
            for (int k = 0; k < KC; k++) {
                float4 a = *(const float4*)&As[k][ty * 4];
                float4 b = *(const float4*)&Bs[k][tx * 4];
                acc[0][0] += a.x * b.x; acc[0][1] += a.x * b.y; acc[0][2] += a.x * b.z; acc[0][3] += a.x * b.w;
                acc[1][0] += a.y * b.x; acc[1][1] += a.y * b.y; acc[1][2] += a.y * b.z; acc[1][3] += a.y * b.w;
                acc[2][0] += a.z * b.x; acc[2][1] += a.z * b.y; acc[2][2] += a.z * b.z; acc[2][3] += a.z * b.w;
                acc[3][0] += a.w * b.x; acc[3][1] += a.w * b.y; acc[3][2] += a.w * b.z; acc[3][3] += a.w * b.w;
            }
        }

        float lmin = __int_as_float(0x7F800000);
#pragma unroll
        for (int r = 0; r < 4; r++) {
            int gi = bi * PT + ty * 4 + r;
            if (gi >= NUM_CLASSES) continue;
            float sqi = g_sq[gi];
#pragma unroll
            for (int s2 = 0; s2 < 4; s2++) {
                int gj = bj * PT + tx * 4 + s2;
                if (gj >= NUM_CLASSES) continue;
                float dis = sqi + g_sq[gj] - 2.0f * acc[r][s2];
                if (dis > 0.0f) lmin = fminf(lmin, dis);
            }
        }
        // warp-reduce then one atomic per warp
#pragma unroll
        for (int off = 16; off > 0; off >>= 1)
            lmin = fminf(lmin, __shfl_down_sync(0xFFFFFFFF, lmin, off));
        if ((tid & 31) == 0 && lmin < __int_as_float(0x7F800000))
            atomicMin(&g_minbits, __float_as_int(lmin));
    }

    // last-block finalize (all GRID_PW*GRID_PW blocks participate)
    __syncthreads();
    if (tid == 0) {
        __threadfence();
        int d = atomicAdd(&g_done, 1);
        if (d == GRID_PW * GRID_PW - 1) {
            float dmin = __int_as_float(atomicAdd(&g_minbits, 0));
            out[0] = fmaxf(1.0f - dmin, 0.0f);  // MARGIN_INTER=1, BETA=1
        }
    }
}

extern "C" void kernel_launch(void* const* d_in, const int* in_sizes, int n_in,
                              void* d_out, int out_size) {
    const float* features = (const float*)d_in[0];
    const void*  labels   = d_in[1];
    int n = in_sizes[1];
    float* out = (float*)d_out;

    k_init<<<1, 1024>>>(labels);
    k_hist<<<(n + 255) / 256, 256>>>(labels, n);
    k_scan<<<1, 1024>>>(n);
    k_scatter<<<(n + 255) / 256, 256>>>(labels, n);
    k_classsum<<<NUM_CLASSES, D>>>(features);
    dim3 pg(GRID_PW, GRID_PW);
    k_pairwise<<<pg, 256>>>(out);
}